// round 10
// baseline (speedup 1.0000x reference)
#include <cuda_runtime.h>
#include <cuda_bf16.h>
#include <cstdint>

#define NN 256
#define LL 256
#define BB 16384

#if defined(__CUDA_ARCH_FEAT_SM103_ALL) || defined(__CUDA_ARCH_FEAT_SM100_ALL) || defined(__CUDA_ARCH_FEAT_SM101_ALL)
#define HAS_TC 1
#else
#define HAS_TC 0
#endif

typedef unsigned long long u64;

// ---------------- scratch ----------------
__device__ float4 g_C[LL * NN];   // packed coeffs (diag.x, diag.y, off.x, off.y)
// Deduplicated B images: Wr/Wi bf16 hi/lo as pre-swizzled 16KB SMEM tile images per 32-k chunk.
__device__ __align__(128) __nv_bfloat16 g_Wrh[256 * 256];
__device__ __align__(128) __nv_bfloat16 g_Wrl[256 * 256];
__device__ __align__(128) __nv_bfloat16 g_Wih[256 * 256];
__device__ __align__(128) __nv_bfloat16 g_Wil[256 * 256];

// ---------------- common helpers ----------------
__device__ __forceinline__ uint32_t smem_u32(const void* p) {
    uint32_t a;
    asm("{ .reg .u64 t; cvta.to.shared.u64 t, %1; cvt.u32.u64 %0, t; }" : "=r"(a) : "l"(p));
    return a;
}
__device__ __forceinline__ float2 cmul(float2 a, float2 b) {
    return make_float2(a.x * b.x - a.y * b.y, a.x * b.y + a.y * b.x);
}
union BU { __nv_bfloat162 h; uint32_t u; };
union F2U { float2 f; u64 u; };

#define FMA_F32X2(d, a, b) \
    asm("fma.rn.f32x2 %0, %1, %2, %0;" : "+l"(d) : "l"(a), "l"(b))
#define MUL_F32X2(d, a, b) \
    asm("mul.rn.f32x2 %0, %1, %2;" : "=l"(d) : "l"(a), "l"(b))
__device__ __forceinline__ u64 pack2(float lo, float hi) {
    u64 r; asm("mov.b64 %0, {%1,%2};" : "=l"(r) : "f"(lo), "f"(hi)); return r;
}
__device__ __forceinline__ u64 dup2(float x) {
    u64 r; asm("mov.b64 %0, {%1,%1};" : "=l"(r) : "f"(x)); return r;
}

// ---------------- tcgen05 / async helpers ----------------
#define TCGEN05_ALLOC_CG2(sa, n) \
    asm volatile("tcgen05.alloc.cta_group::2.sync.aligned.shared::cta.b32 [%0], %1;" :: "r"((uint32_t)(sa)), "r"((uint32_t)(n)) : "memory")
#define TCGEN05_DEALLOC_CG2(t, n) \
    asm volatile("tcgen05.dealloc.cta_group::2.sync.aligned.b32 %0, %1;" :: "r"(t), "r"((uint32_t)(n)))
#define TCGEN05_RELINQ_CG2() \
    asm volatile("tcgen05.relinquish_alloc_permit.cta_group::2.sync.aligned;")
#define TCGEN05_COMMIT_MC_CG2(mb, mask) \
    asm volatile("tcgen05.commit.cta_group::2.mbarrier::arrive::one.shared::cluster.multicast::cluster.b64 [%0], %1;" \
        :: "r"((uint32_t)(mb)), "h"((uint16_t)(mask)) : "memory")
#define TCGEN05_WAIT_LD() asm volatile("tcgen05.wait::ld.sync.aligned;" ::: "memory")
#define TCGEN05_FENCE_AFTER() asm volatile("tcgen05.fence::after_thread_sync;" ::: "memory")
#define FENCE_ASYNC_SHARED() asm volatile("fence.proxy.async.shared::cta;" ::: "memory")
#define CLUSTER_SYNC() do { \
    asm volatile("barrier.cluster.arrive.aligned;" ::: "memory"); \
    asm volatile("barrier.cluster.wait.aligned;" ::: "memory"); \
} while (0)

#define MBARRIER_INIT(mb, cnt) \
    asm volatile("mbarrier.init.shared.b64 [%0], %1;" :: "r"((uint32_t)(mb)), "r"((uint32_t)(cnt)) : "memory")
#define MBARRIER_ARRIVE(mb) \
    asm volatile("mbarrier.arrive.shared.b64 _, [%0];" :: "r"((uint32_t)(mb)) : "memory")
#define MBARRIER_ARRIVE_LEADER(mb) \
    asm volatile("{\n\t.reg .b32 la;\n\tand.b32 la, %0, 0xFEFFFFFF;\n\tmbarrier.arrive.shared::cluster.b64 _, [la];\n\t}" \
        :: "r"((uint32_t)(mb)) : "memory")
#define MBARRIER_EXPECT_TX(mb, tx) \
    asm volatile("mbarrier.arrive.expect_tx.shared.b64 _, [%0], %1;" :: "r"((uint32_t)(mb)), "r"((uint32_t)(tx)) : "memory")
#define MBARRIER_WAIT_PARITY(mb, ph) do { \
    uint32_t _mb = (uint32_t)(mb), _ph = (uint32_t)(ph), _done; \
    asm volatile("{\n\t.reg .pred p;\n\tmbarrier.try_wait.parity.acquire.cta.shared::cta.b64 p, [%1], %2;\n\tselp.b32 %0, 1, 0, p;\n\t}" \
        : "=r"(_done) : "r"(_mb), "r"(_ph) : "memory"); \
    if (!_done) { \
        asm volatile("{\n\t.reg .pred P1;\n\tWL_%=:\n\tmbarrier.try_wait.parity.acquire.cta.shared::cta.b64 P1, [%0], %1, 0x989680;\n\t@P1 bra.uni WD_%=;\n\tbra.uni WL_%=;\n\tWD_%=:\n\t}" \
            :: "r"(_mb), "r"(_ph) : "memory"); \
    } } while (0)
#define MBARRIER_WAIT_PARITY_CLU(mb, ph) do { \
    uint32_t _mb = (uint32_t)(mb), _ph = (uint32_t)(ph), _done; \
    asm volatile("{\n\t.reg .pred p;\n\tmbarrier.try_wait.parity.acquire.cluster.shared::cta.b64 p, [%1], %2;\n\tselp.b32 %0, 1, 0, p;\n\t}" \
        : "=r"(_done) : "r"(_mb), "r"(_ph) : "memory"); \
    if (!_done) { \
        asm volatile("{\n\t.reg .pred P1;\n\tWL_%=:\n\tmbarrier.try_wait.parity.acquire.cluster.shared::cta.b64 P1, [%0], %1, 0x989680;\n\t@P1 bra.uni WD_%=;\n\tbra.uni WL_%=;\n\tWD_%=:\n\t}" \
            :: "r"(_mb), "r"(_ph) : "memory"); \
    } } while (0)

#define CP_ASYNC_BULK(dst, src, bytes, mb) \
    asm volatile("cp.async.bulk.shared::cluster.global.mbarrier::complete_tx::bytes [%0], [%1], %2, [%3];" \
        :: "r"((uint32_t)(dst)), "l"(src), "r"((uint32_t)(bytes)), "r"((uint32_t)(mb)) : "memory")

#define TCGEN05_LD_32X32B_X32(r, ta) \
    asm volatile("tcgen05.ld.sync.aligned.32x32b.x32.b32 " \
        "{%0,%1,%2,%3,%4,%5,%6,%7,%8,%9,%10,%11,%12,%13,%14,%15," \
        "%16,%17,%18,%19,%20,%21,%22,%23,%24,%25,%26,%27,%28,%29,%30,%31}, [%32];" \
        : "=r"((r)[0]), "=r"((r)[1]), "=r"((r)[2]), "=r"((r)[3]), "=r"((r)[4]), "=r"((r)[5]), "=r"((r)[6]), "=r"((r)[7]), \
          "=r"((r)[8]), "=r"((r)[9]), "=r"((r)[10]), "=r"((r)[11]), "=r"((r)[12]), "=r"((r)[13]), "=r"((r)[14]), "=r"((r)[15]), \
          "=r"((r)[16]), "=r"((r)[17]), "=r"((r)[18]), "=r"((r)[19]), "=r"((r)[20]), "=r"((r)[21]), "=r"((r)[22]), "=r"((r)[23]), \
          "=r"((r)[24]), "=r"((r)[25]), "=r"((r)[26]), "=r"((r)[27]), "=r"((r)[28]), "=r"((r)[29]), "=r"((r)[30]), "=r"((r)[31]) \
        : "r"(ta))

#define SWZ64(o) ((o) ^ (((o) >> 3) & 0x30))

#if HAS_TC
__device__ __forceinline__ uint32_t elect_one_pred() {
    uint32_t p;
    asm volatile("{\n\t.reg .pred p;\n\telect.sync _|p, 0xFFFFFFFF;\n\tselp.b32 %0, 1, 0, p;\n\t}" : "=r"(p));
    return p;
}
__device__ __forceinline__ uint32_t cluster_rank() {
    uint32_t r; asm("mov.u32 %0, %%cluster_ctarank;" : "=r"(r)); return r;
}
// SW64 K-major descriptor
__device__ __forceinline__ uint64_t make_desc_sw64(uint32_t base) {
    return ((uint64_t)4 << 61) | ((uint64_t)1 << 46) | ((uint64_t)32 << 32) | ((uint64_t)1 << 16)
         | (uint64_t)((base >> 4) & 0x3FFF);
}
__device__ __forceinline__ void mma_f16_ss_cg2(uint32_t d, uint64_t ad, uint64_t bd,
                                               uint32_t idesc, uint32_t en) {
    asm volatile(
        "{\n\t.reg .pred p;\n\tsetp.ne.u32 p, %5, 0;\n\t"
        "tcgen05.mma.cta_group::2.kind::f16 [%0], %1, %2, %3, {%4,%4,%4,%4,%4,%4,%4,%4}, p;\n\t}"
        :: "r"(d), "l"(ad), "l"(bd), "r"(idesc), "r"(0u), "r"(en) : "memory");
}
#endif

// ---------------- kernel 1: per-layer MZI coefficients ----------------
__global__ void coeff_kernel(const float* __restrict__ theta,
                             const float* __restrict__ phi) {
    __shared__ float2 ips[NN];
    __shared__ float2 eps[NN];
    __shared__ float2 offs[NN];
    int l = blockIdx.x;
    int n = threadIdx.x;
    const float* th = theta + l * (NN / 2);
    const float* ph = phi + l * (NN / 2);

    {
        float ang = 0.5f * th[n >> 1];
        if (n & 1) ang = -ang;
        float s, c; sincosf(ang, &s, &c);
        ips[n] = make_float2(c, s);
        if (n & 1) eps[n] = make_float2(1.f, 0.f);
        else { float s2, c2; sincosf(ph[n >> 1], &s2, &c2); eps[n] = make_float2(c2, s2); }
    }
    __syncthreads();

    int nm = (n - 1) & (NN - 1), np = (n + 1) & (NN - 1);
    float2 p0 = ips[nm], p1 = ips[n], p2 = ips[np];
    float2 v = make_float2(2.f * p1.x - p2.x - p0.x, 2.f * p1.y - p2.y - p0.y);
    float2 u = make_float2(2.f * p1.x + p2.x + p0.x, 2.f * p1.y + p2.y + p0.y);
    float2 en = eps[n], ep = eps[nm];

    float2 diag = cmul(en, v); diag.x *= 0.25f; diag.y *= 0.25f;
    float2 iu = make_float2(-u.y, u.x);
    float2 off = cmul(ep, iu); off.x *= 0.25f; off.y *= 0.25f;

    offs[n ^ 1] = off;
    __syncthreads();
    float2 o = offs[n];
    g_C[l * NN + n] = make_float4(diag.x, diag.y, o.x, o.y);
}

// ---------------- kernel 2: compose W — fused layer pairs, packed coeffs ----------------
#define RB 2
__global__ __launch_bounds__(NN) void build_w_kernel(const float* __restrict__ gamma) {
    __shared__ float2 bufA[RB][NN];
    __shared__ float2 bufB[RB][NN];
    int i = threadIdx.x;
    int r0 = blockIdx.x * RB;

#pragma unroll
    for (int r = 0; r < RB; r++) {
        int j = r0 + r;
        float2 v = make_float2(0.f, 0.f);
        if (i == j) { float s, c; sincosf(gamma[j], &s, &c); v = make_float2(c, s); }
        bufA[r][i] = v;
    }

    const int M = NN - 1;
    int odd = i & 1;
    int xa1 = odd ? (i + 1) & M : (i - 1) & M;
    int xb0 = odd ? (i - 1) & M : (i + 1) & M;
    int xb1 = odd ? (i - 2) & M : (i + 2) & M;
    int ca = (i - 1) & M;
    int cb = odd ? (i - 2) & M : i;

    float4 c0 = g_C[i];
    float4 cL = g_C[255 * NN + i];

    float4 qa[2], qb[2], q2[2];
#pragma unroll
    for (int p = 0; p < 2; p++) {
        qa[p] = g_C[(2 * p + 1) * NN + ca];
        qb[p] = g_C[(2 * p + 1) * NN + cb];
        q2[p] = g_C[(2 * p + 2) * NN + i];
    }
    __syncthreads();

    float2 (*A)[NN] = bufA;
    float2 (*Bx)[NN] = bufB;

    // ---- layer 0 (s=0)
    {
        u64 D1 = pack2(c0.x, c0.y), D2 = pack2(-c0.y, c0.x);
        u64 O1 = pack2(c0.z, c0.w), O2 = pack2(-c0.w, c0.z);
#pragma unroll
        for (int r = 0; r < RB; r++) {
            float2 t = A[r][i], u = A[r][i ^ 1];
            u64 w;
            MUL_F32X2(w, dup2(t.x), D1);
            FMA_F32X2(w, dup2(t.y), D2);
            FMA_F32X2(w, dup2(u.x), O1);
            FMA_F32X2(w, dup2(u.y), O2);
            F2U cv; cv.u = w; Bx[r][i] = cv.f;
        }
        __syncthreads();
        float2 (*tmp)[NN] = A; A = Bx; Bx = tmp;
    }

    // ---- 127 fused pairs
    for (int p = 0; p < 127; ++p) {
        int sl = p & 1;
        float4 a4 = qa[sl], b4 = qb[sl], d4 = q2[sl];
        if (p + 2 < 127) {
            int pp = p + 2;
            qa[sl] = g_C[(2 * pp + 1) * NN + ca];
            qb[sl] = g_C[(2 * pp + 1) * NN + cb];
            q2[sl] = g_C[(2 * pp + 2) * NN + i];
        }
        u64 A1 = pack2(a4.x, a4.y), A2 = pack2(-a4.y, a4.x);
        u64 Oa1 = pack2(a4.z, a4.w), Oa2 = pack2(-a4.w, a4.z);
        u64 B1 = pack2(b4.x, b4.y), B2 = pack2(-b4.y, b4.x);
        u64 Ob1 = pack2(b4.z, b4.w), Ob2 = pack2(-b4.w, b4.z);
        u64 D1 = pack2(d4.x, d4.y), D2 = pack2(-d4.y, d4.x);
        u64 Q1 = pack2(d4.z, d4.w), Q2 = pack2(-d4.w, d4.z);
#pragma unroll
        for (int r = 0; r < RB; r++) {
            float2 va0 = A[r][i],  va1 = A[r][xa1];
            float2 vb0 = A[r][xb0], vb1 = A[r][xb1];
            u64 ma, mb, w;
            MUL_F32X2(ma, dup2(va0.x), A1);
            FMA_F32X2(ma, dup2(va0.y), A2);
            FMA_F32X2(ma, dup2(va1.x), Oa1);
            FMA_F32X2(ma, dup2(va1.y), Oa2);
            MUL_F32X2(mb, dup2(vb0.x), B1);
            FMA_F32X2(mb, dup2(vb0.y), B2);
            FMA_F32X2(mb, dup2(vb1.x), Ob1);
            FMA_F32X2(mb, dup2(vb1.y), Ob2);
            F2U fa; fa.u = ma; F2U fb; fb.u = mb;
            MUL_F32X2(w, dup2(fa.f.x), D1);
            FMA_F32X2(w, dup2(fa.f.y), D2);
            FMA_F32X2(w, dup2(fb.f.x), Q1);
            FMA_F32X2(w, dup2(fb.f.y), Q2);
            F2U cv; cv.u = w; Bx[r][i] = cv.f;
        }
        __syncthreads();
        float2 (*tmp)[NN] = A; A = Bx; Bx = tmp;
    }

    // ---- layer 255 (s=+1)
    {
        int ia = (i + 1) & M;
        int ib = ((i ^ 1) + 1) & M;
        u64 D1 = pack2(cL.x, cL.y), D2 = pack2(-cL.y, cL.x);
        u64 O1 = pack2(cL.z, cL.w), O2 = pack2(-cL.w, cL.z);
#pragma unroll
        for (int r = 0; r < RB; r++) {
            float2 t = A[r][ia], u = A[r][ib];
            u64 w;
            MUL_F32X2(w, dup2(t.x), D1);
            FMA_F32X2(w, dup2(t.y), D2);
            FMA_F32X2(w, dup2(u.x), O1);
            FMA_F32X2(w, dup2(u.y), O2);
            F2U cv; cv.u = w; Bx[r][i] = cv.f;
        }
        __syncthreads();
        float2 (*tmp)[NN] = A; A = Bx; Bx = tmp;
    }

    auto store_b = [](__nv_bfloat16* img, int n, int k, __nv_bfloat16 v) {
        uint32_t off = ((uint32_t)k >> 5) * 16384u + SWZ64((uint32_t)(n * 64 + (k & 31) * 2));
        *(__nv_bfloat16*)((char*)img + off) = v;
    };

    int src = (i - 1) & M;
#pragma unroll
    for (int r = 0; r < RB; r++) {
        float2 w = A[r][src];
        int k = r0 + r, n = i;
        __nv_bfloat16 hr = __float2bfloat16(w.x);
        __nv_bfloat16 lr = __float2bfloat16(w.x - __bfloat162float(hr));
        __nv_bfloat16 hi = __float2bfloat16(w.y);
        __nv_bfloat16 li = __float2bfloat16(w.y - __bfloat162float(hi));
        store_b(g_Wrh, n, k, hr);
        store_b(g_Wrl, n, k, lr);
        store_b(g_Wih, n, k, hi);
        store_b(g_Wil, n, k, li);
    }
}

// ---------------- kernel 2.5: no-op spacer ----------------
__global__ void probe_kernel() {}

// ---------------- kernel 3: tcgen05 cg2 GEMM, 3-stage ring, negate-A idesc ----------------
// Per stage per CTA: A = XR_H/L, XI_H/L (32KB); B = WR_H/L, WI_H/L halves (32KB).
#define KC 32
#define SMEM_TMEM 0
#define MB_FULL(s)  (16 + (s) * 8)   // 3 slots: 4 A-warps + B expect_tx
#define MB_EMPTY(s) (40 + (s) * 8)   // 3 slots: multicast from leader commit
#define MB_LEAD(s)  (64 + (s) * 8)   // 3 slots on leader: 2 relay arrivals
#define MB_DONE     88
#define XR_H 0
#define XR_L 8192
#define XI_H 16384
#define XI_L 24576
#define WR_H 32768
#define WR_L 40960
#define WI_H 49152
#define WI_L 57344
#define STAGE_SZ 65536
#define STAGE_BASE(s) (1024 + (s) * STAGE_SZ)
#define SMEM_TOTAL (1024 + 3 * STAGE_SZ)
#define NSTG 3

__global__ __launch_bounds__(256, 1) __cluster_dims__(2, 1, 1)
void gemm_tc_kernel(const float* __restrict__ xre, const float* __restrict__ xim,
                    float* __restrict__ out) {
#if HAS_TC
    extern __shared__ char smem[];
    const uint32_t sb = smem_u32(smem);
    int tid = threadIdx.x, wid = tid >> 5, lane = tid & 31;
    int m0 = blockIdx.x * 128;
    uint32_t rank = cluster_rank();

    if (wid == 4) TCGEN05_ALLOC_CG2(sb + SMEM_TMEM, 512);
    if (tid == 0) {
#pragma unroll
        for (int s = 0; s < NSTG; ++s) {
            MBARRIER_INIT(sb + MB_FULL(s), 5);
            MBARRIER_INIT(sb + MB_EMPTY(s), 1);
            MBARRIER_INIT(sb + MB_LEAD(s), 2);
        }
        MBARRIER_INIT(sb + MB_DONE, 1);
    }
    __syncthreads();
    CLUSTER_SYNC();
    uint32_t tmem;
    asm volatile("ld.shared.b32 %0, [%1];" : "=r"(tmem) : "r"(sb + SMEM_TMEM));

    if (wid < 4) {
        // ---- A producer: register-prefetched fp32 -> bf16 hi/lo
        float4 buf[16];
#pragma unroll
        for (int j = 0; j < 16; ++j) {
            int pl = j >> 3;
            int g = (j & 7) * 128 + tid;
            int rr = g >> 3, f4 = g & 7;
            const float* plane = pl ? xim : xre;
            buf[j] = *(const float4*)(plane + (size_t)(m0 + rr) * NN + f4 * 4);
        }
        for (int it = 0; it < 8; ++it) {
            int s = it % NSTG;
            if (it >= NSTG) MBARRIER_WAIT_PARITY(sb + MB_EMPTY(s), ((it - NSTG) / NSTG) & 1);
            uint32_t stage = sb + STAGE_BASE(s);
            int kcn = (it + 1) * KC;
            bool more = (it < 7);
#pragma unroll
            for (int j = 0; j < 16; ++j) {
                int pl = j >> 3;
                int g = (j & 7) * 128 + tid;
                int rr = g >> 3, f4 = g & 7;
                float4 v = buf[j];
                if (more) {
                    const float* plane = pl ? xim : xre;
                    buf[j] = *(const float4*)(plane + (size_t)(m0 + rr) * NN + kcn + f4 * 4);
                }
                BU h0, h1, l0, l1;
                h0.h = __floats2bfloat162_rn(v.x, v.y);
                h1.h = __floats2bfloat162_rn(v.z, v.w);
                float2 f0 = __bfloat1622float2(h0.h), f1 = __bfloat1622float2(h1.h);
                l0.h = __floats2bfloat162_rn(v.x - f0.x, v.y - f0.y);
                l1.h = __floats2bfloat162_rn(v.z - f1.x, v.w - f1.y);
                uint32_t off = SWZ64((uint32_t)(rr * 64 + f4 * 8));
                uint32_t hdst = stage + (pl ? XI_H : XR_H) + off;
                uint32_t ldst = stage + (pl ? XI_L : XR_L) + off;
                asm volatile("st.shared.v2.b32 [%0], {%1,%2};" :: "r"(hdst), "r"(h0.u), "r"(h1.u) : "memory");
                asm volatile("st.shared.v2.b32 [%0], {%1,%2};" :: "r"(ldst), "r"(l0.u), "r"(l1.u) : "memory");
            }
            FENCE_ASYNC_SHARED();
            __syncwarp();
            if (lane == 0) MBARRIER_ARRIVE(sb + MB_FULL(s));
        }
    } else if (wid == 5) {
        // ---- B producer: this CTA's half of each image (rank-offset 8KB slices)
        for (int it = 0; it < 8; ++it) {
            int s = it % NSTG;
            if (it >= NSTG) MBARRIER_WAIT_PARITY(sb + MB_EMPTY(s), ((it - NSTG) / NSTG) & 1);
            if (elect_one_pred()) {
                uint32_t mb = sb + MB_FULL(s);
                uint32_t stage = sb + STAGE_BASE(s);
                size_t co = (size_t)it * 16384 + (size_t)rank * 8192;
                MBARRIER_EXPECT_TX(mb, 32768);
                CP_ASYNC_BULK(stage + WR_H, (const char*)g_Wrh + co, 8192, mb);
                CP_ASYNC_BULK(stage + WR_L, (const char*)g_Wrl + co, 8192, mb);
                CP_ASYNC_BULK(stage + WI_H, (const char*)g_Wih + co, 8192, mb);
                CP_ASYNC_BULK(stage + WI_L, (const char*)g_Wil + co, 8192, mb);
            }
        }
    } else if (wid == 6) {
        // ---- relay: forward local readiness to leader
        for (int it = 0; it < 8; ++it) {
            int s = it % NSTG;
            MBARRIER_WAIT_PARITY(sb + MB_FULL(s), (it / NSTG) & 1);
            if (elect_one_pred()) MBARRIER_ARRIVE_LEADER(sb + MB_LEAD(s));
        }
    } else if (wid == 4 && rank == 0) {
        // ---- MMA warp (leader): 12 groups x 2 kk; negate-A (idesc bit 13) on Yr's Xi terms
        const uint32_t IDESC = (1u << 4) | (1u << 7) | (1u << 10) | (32u << 17) | (16u << 24);
        const uint32_t NEG_A = 1u << 13;
        const uint32_t aoff[12] = {XR_H, XR_L, XR_H, XI_H, XI_L, XI_H,
                                   XR_H, XR_L, XR_H, XI_H, XI_L, XI_H};
        const uint32_t boff[12] = {WR_H, WR_H, WR_L, WI_H, WI_H, WI_L,
                                   WI_H, WI_H, WI_L, WR_H, WR_H, WR_L};
        uint64_t dbase[NSTG];
#pragma unroll
        for (int s = 0; s < NSTG; ++s) dbase[s] = make_desc_sw64(sb + STAGE_BASE(s));
        for (int it = 0; it < 8; ++it) {
            int s = it % NSTG;
            MBARRIER_WAIT_PARITY_CLU(sb + MB_LEAD(s), (it / NSTG) & 1);
            if (elect_one_pred()) {
                uint64_t db = dbase[s];
#pragma unroll
                for (int g = 0; g < 12; ++g) {
                    uint64_t ad = db + (aoff[g] >> 4);
                    uint64_t bd = db + (boff[g] >> 4);
                    uint32_t dreg = tmem + ((g >= 6) ? 256 : 0);
                    uint32_t idesc = IDESC | ((g >= 3 && g < 6) ? NEG_A : 0u);
#pragma unroll
                    for (int kk = 0; kk < 2; ++kk) {
                        uint32_t en = !(it == 0 && kk == 0 && (g == 0 || g == 6));
                        mma_f16_ss_cg2(dreg, ad + kk * 2, bd + kk * 2, idesc, en);
                    }
                }
                TCGEN05_COMMIT_MC_CG2((it == 7) ? (sb + MB_DONE) : (sb + MB_EMPTY(s)), 0x3);
            }
        }
    }
    // warp 7 (and rank1 warp 4): fall through to epilogue wait

    // ---- epilogue
    MBARRIER_WAIT_PARITY(sb + MB_DONE, 0);
    TCGEN05_FENCE_AFTER();
    {
        int wg = tid >> 7;
        int wt = tid & 127;
        int m = m0 + wt;
        float* dst = out + (size_t)wg * BB * NN + (size_t)m * NN;
        uint32_t colbase = tmem + wg * 256;
#pragma unroll
        for (int c = 0; c < 8; ++c) {
            uint32_t r[32];
            TCGEN05_LD_32X32B_X32(r, colbase + c * 32);
            TCGEN05_WAIT_LD();
            float4* d4 = (float4*)(dst + c * 32);
#pragma unroll
            for (int q = 0; q < 8; ++q)
                d4[q] = make_float4(__uint_as_float(r[4 * q]), __uint_as_float(r[4 * q + 1]),
                                    __uint_as_float(r[4 * q + 2]), __uint_as_float(r[4 * q + 3]));
        }
    }
    __syncthreads();
    if (wid == 4) {
        TCGEN05_RELINQ_CG2();
        TCGEN05_DEALLOC_CG2(tmem, 512);
    }
    CLUSTER_SYNC();
#endif  // HAS_TC
}

// ---------------- launch ----------------
extern "C" void kernel_launch(void* const* d_in, const int* in_sizes, int n_in,
                              void* d_out, int out_size) {
    const float* x_re  = (const float*)d_in[0];
    const float* x_im  = (const float*)d_in[1];
    const float* theta = (const float*)d_in[2];
    const float* phi   = (const float*)d_in[3];
    const float* gamma = (const float*)d_in[4];
    float* out = (float*)d_out;

    cudaFuncSetAttribute(gemm_tc_kernel, cudaFuncAttributeMaxDynamicSharedMemorySize, SMEM_TOTAL);

    coeff_kernel<<<LL, NN>>>(theta, phi);
    build_w_kernel<<<NN / RB, NN>>>(gamma);
    probe_kernel<<<1, 32>>>();
    gemm_tc_kernel<<<BB / 128, 256, SMEM_TOTAL>>>(x_re, x_im, out);
}

// round 11
// speedup vs baseline: 1.0250x; 1.0250x over previous
#include <cuda_runtime.h>
#include <cuda_bf16.h>
#include <cstdint>

#define NN 256
#define LL 256
#define BB 16384

#if defined(__CUDA_ARCH_FEAT_SM103_ALL) || defined(__CUDA_ARCH_FEAT_SM100_ALL) || defined(__CUDA_ARCH_FEAT_SM101_ALL)
#define HAS_TC 1
#else
#define HAS_TC 0
#endif

typedef unsigned long long u64;

// ---------------- scratch ----------------
__device__ float4 g_C[LL * NN];   // packed coeffs (diag.x, diag.y, off.x, off.y)
// Deduplicated B images: Wr/Wi bf16 hi/lo as pre-swizzled 16KB SMEM tile images per 32-k chunk.
__device__ __align__(128) __nv_bfloat16 g_Wrh[256 * 256];
__device__ __align__(128) __nv_bfloat16 g_Wrl[256 * 256];
__device__ __align__(128) __nv_bfloat16 g_Wih[256 * 256];
__device__ __align__(128) __nv_bfloat16 g_Wil[256 * 256];

// ---------------- common helpers ----------------
__device__ __forceinline__ uint32_t smem_u32(const void* p) {
    uint32_t a;
    asm("{ .reg .u64 t; cvta.to.shared.u64 t, %1; cvt.u32.u64 %0, t; }" : "=r"(a) : "l"(p));
    return a;
}
__device__ __forceinline__ float2 cmul(float2 a, float2 b) {
    return make_float2(a.x * b.x - a.y * b.y, a.x * b.y + a.y * b.x);
}
union BU { __nv_bfloat162 h; uint32_t u; };
union F2U { float2 f; u64 u; };

#define FMA_F32X2(d, a, b) \
    asm("fma.rn.f32x2 %0, %1, %2, %0;" : "+l"(d) : "l"(a), "l"(b))
#define MUL_F32X2(d, a, b) \
    asm("mul.rn.f32x2 %0, %1, %2;" : "=l"(d) : "l"(a), "l"(b))
__device__ __forceinline__ u64 pack2(float lo, float hi) {
    u64 r; asm("mov.b64 %0, {%1,%2};" : "=l"(r) : "f"(lo), "f"(hi)); return r;
}
__device__ __forceinline__ u64 dup2(float x) {
    u64 r; asm("mov.b64 %0, {%1,%1};" : "=l"(r) : "f"(x)); return r;
}

// ---------------- tcgen05 / async helpers ----------------
#define TCGEN05_ALLOC_CG2(sa, n) \
    asm volatile("tcgen05.alloc.cta_group::2.sync.aligned.shared::cta.b32 [%0], %1;" :: "r"((uint32_t)(sa)), "r"((uint32_t)(n)) : "memory")
#define TCGEN05_DEALLOC_CG2(t, n) \
    asm volatile("tcgen05.dealloc.cta_group::2.sync.aligned.b32 %0, %1;" :: "r"(t), "r"((uint32_t)(n)))
#define TCGEN05_RELINQ_CG2() \
    asm volatile("tcgen05.relinquish_alloc_permit.cta_group::2.sync.aligned;")
#define TCGEN05_COMMIT_MC_CG2(mb, mask) \
    asm volatile("tcgen05.commit.cta_group::2.mbarrier::arrive::one.shared::cluster.multicast::cluster.b64 [%0], %1;" \
        :: "r"((uint32_t)(mb)), "h"((uint16_t)(mask)) : "memory")
#define TCGEN05_WAIT_LD() asm volatile("tcgen05.wait::ld.sync.aligned;" ::: "memory")
#define TCGEN05_FENCE_AFTER() asm volatile("tcgen05.fence::after_thread_sync;" ::: "memory")
#define FENCE_ASYNC_SHARED() asm volatile("fence.proxy.async.shared::cta;" ::: "memory")
#define CLUSTER_SYNC() do { \
    asm volatile("barrier.cluster.arrive.aligned;" ::: "memory"); \
    asm volatile("barrier.cluster.wait.aligned;" ::: "memory"); \
} while (0)

#define MBARRIER_INIT(mb, cnt) \
    asm volatile("mbarrier.init.shared.b64 [%0], %1;" :: "r"((uint32_t)(mb)), "r"((uint32_t)(cnt)) : "memory")
#define MBARRIER_ARRIVE(mb) \
    asm volatile("mbarrier.arrive.shared.b64 _, [%0];" :: "r"((uint32_t)(mb)) : "memory")
#define MBARRIER_ARRIVE_LEADER(mb) \
    asm volatile("{\n\t.reg .b32 la;\n\tand.b32 la, %0, 0xFEFFFFFF;\n\tmbarrier.arrive.shared::cluster.b64 _, [la];\n\t}" \
        :: "r"((uint32_t)(mb)) : "memory")
#define MBARRIER_EXPECT_TX(mb, tx) \
    asm volatile("mbarrier.arrive.expect_tx.shared.b64 _, [%0], %1;" :: "r"((uint32_t)(mb)), "r"((uint32_t)(tx)) : "memory")
#define MBARRIER_WAIT_PARITY(mb, ph) do { \
    uint32_t _mb = (uint32_t)(mb), _ph = (uint32_t)(ph), _done; \
    asm volatile("{\n\t.reg .pred p;\n\tmbarrier.try_wait.parity.acquire.cta.shared::cta.b64 p, [%1], %2;\n\tselp.b32 %0, 1, 0, p;\n\t}" \
        : "=r"(_done) : "r"(_mb), "r"(_ph) : "memory"); \
    if (!_done) { \
        asm volatile("{\n\t.reg .pred P1;\n\tWL_%=:\n\tmbarrier.try_wait.parity.acquire.cta.shared::cta.b64 P1, [%0], %1, 0x989680;\n\t@P1 bra.uni WD_%=;\n\tbra.uni WL_%=;\n\tWD_%=:\n\t}" \
            :: "r"(_mb), "r"(_ph) : "memory"); \
    } } while (0)
#define MBARRIER_WAIT_PARITY_CLU(mb, ph) do { \
    uint32_t _mb = (uint32_t)(mb), _ph = (uint32_t)(ph), _done; \
    asm volatile("{\n\t.reg .pred p;\n\tmbarrier.try_wait.parity.acquire.cluster.shared::cta.b64 p, [%1], %2;\n\tselp.b32 %0, 1, 0, p;\n\t}" \
        : "=r"(_done) : "r"(_mb), "r"(_ph) : "memory"); \
    if (!_done) { \
        asm volatile("{\n\t.reg .pred P1;\n\tWL_%=:\n\tmbarrier.try_wait.parity.acquire.cluster.shared::cta.b64 P1, [%0], %1, 0x989680;\n\t@P1 bra.uni WD_%=;\n\tbra.uni WL_%=;\n\tWD_%=:\n\t}" \
            :: "r"(_mb), "r"(_ph) : "memory"); \
    } } while (0)

#define CP_ASYNC_BULK(dst, src, bytes, mb) \
    asm volatile("cp.async.bulk.shared::cluster.global.mbarrier::complete_tx::bytes [%0], [%1], %2, [%3];" \
        :: "r"((uint32_t)(dst)), "l"(src), "r"((uint32_t)(bytes)), "r"((uint32_t)(mb)) : "memory")

#define TCGEN05_LD_32X32B_X32(r, ta) \
    asm volatile("tcgen05.ld.sync.aligned.32x32b.x32.b32 " \
        "{%0,%1,%2,%3,%4,%5,%6,%7,%8,%9,%10,%11,%12,%13,%14,%15," \
        "%16,%17,%18,%19,%20,%21,%22,%23,%24,%25,%26,%27,%28,%29,%30,%31}, [%32];" \
        : "=r"((r)[0]), "=r"((r)[1]), "=r"((r)[2]), "=r"((r)[3]), "=r"((r)[4]), "=r"((r)[5]), "=r"((r)[6]), "=r"((r)[7]), \
          "=r"((r)[8]), "=r"((r)[9]), "=r"((r)[10]), "=r"((r)[11]), "=r"((r)[12]), "=r"((r)[13]), "=r"((r)[14]), "=r"((r)[15]), \
          "=r"((r)[16]), "=r"((r)[17]), "=r"((r)[18]), "=r"((r)[19]), "=r"((r)[20]), "=r"((r)[21]), "=r"((r)[22]), "=r"((r)[23]), \
          "=r"((r)[24]), "=r"((r)[25]), "=r"((r)[26]), "=r"((r)[27]), "=r"((r)[28]), "=r"((r)[29]), "=r"((r)[30]), "=r"((r)[31]) \
        : "r"(ta))

#define SWZ64(o) ((o) ^ (((o) >> 3) & 0x30))

#if HAS_TC
__device__ __forceinline__ uint32_t elect_one_pred() {
    uint32_t p;
    asm volatile("{\n\t.reg .pred p;\n\telect.sync _|p, 0xFFFFFFFF;\n\tselp.b32 %0, 1, 0, p;\n\t}" : "=r"(p));
    return p;
}
__device__ __forceinline__ uint32_t cluster_rank() {
    uint32_t r; asm("mov.u32 %0, %%cluster_ctarank;" : "=r"(r)); return r;
}
// SW64 K-major descriptor
__device__ __forceinline__ uint64_t make_desc_sw64(uint32_t base) {
    return ((uint64_t)4 << 61) | ((uint64_t)1 << 46) | ((uint64_t)32 << 32) | ((uint64_t)1 << 16)
         | (uint64_t)((base >> 4) & 0x3FFF);
}
__device__ __forceinline__ void mma_f16_ss_cg2(uint32_t d, uint64_t ad, uint64_t bd,
                                               uint32_t idesc, uint32_t en) {
    asm volatile(
        "{\n\t.reg .pred p;\n\tsetp.ne.u32 p, %5, 0;\n\t"
        "tcgen05.mma.cta_group::2.kind::f16 [%0], %1, %2, %3, {%4,%4,%4,%4,%4,%4,%4,%4}, p;\n\t}"
        :: "r"(d), "l"(ad), "l"(bd), "r"(idesc), "r"(0u), "r"(en) : "memory");
}
#endif

// ---------------- kernel 1: per-layer MZI coefficients ----------------
__global__ void coeff_kernel(const float* __restrict__ theta,
                             const float* __restrict__ phi) {
    __shared__ float2 ips[NN];
    __shared__ float2 eps[NN];
    __shared__ float2 offs[NN];
    int l = blockIdx.x;
    int n = threadIdx.x;
    const float* th = theta + l * (NN / 2);
    const float* ph = phi + l * (NN / 2);

    {
        float ang = 0.5f * th[n >> 1];
        if (n & 1) ang = -ang;
        float s, c; sincosf(ang, &s, &c);
        ips[n] = make_float2(c, s);
        if (n & 1) eps[n] = make_float2(1.f, 0.f);
        else { float s2, c2; sincosf(ph[n >> 1], &s2, &c2); eps[n] = make_float2(c2, s2); }
    }
    __syncthreads();

    int nm = (n - 1) & (NN - 1), np = (n + 1) & (NN - 1);
    float2 p0 = ips[nm], p1 = ips[n], p2 = ips[np];
    float2 v = make_float2(2.f * p1.x - p2.x - p0.x, 2.f * p1.y - p2.y - p0.y);
    float2 u = make_float2(2.f * p1.x + p2.x + p0.x, 2.f * p1.y + p2.y + p0.y);
    float2 en = eps[n], ep = eps[nm];

    float2 diag = cmul(en, v); diag.x *= 0.25f; diag.y *= 0.25f;
    float2 iu = make_float2(-u.y, u.x);
    float2 off = cmul(ep, iu); off.x *= 0.25f; off.y *= 0.25f;

    offs[n ^ 1] = off;
    __syncthreads();
    float2 o = offs[n];
    g_C[l * NN + n] = make_float4(diag.x, diag.y, o.x, o.y);
}

// ---------------- kernel 2: compose W — fused layer pairs, packed coeffs ----------------
#define RB 2
__global__ __launch_bounds__(NN) void build_w_kernel(const float* __restrict__ gamma) {
    __shared__ float2 bufA[RB][NN];
    __shared__ float2 bufB[RB][NN];
    int i = threadIdx.x;
    int r0 = blockIdx.x * RB;

#pragma unroll
    for (int r = 0; r < RB; r++) {
        int j = r0 + r;
        float2 v = make_float2(0.f, 0.f);
        if (i == j) { float s, c; sincosf(gamma[j], &s, &c); v = make_float2(c, s); }
        bufA[r][i] = v;
    }

    const int M = NN - 1;
    int odd = i & 1;
    int xa1 = odd ? (i + 1) & M : (i - 1) & M;
    int xb0 = odd ? (i - 1) & M : (i + 1) & M;
    int xb1 = odd ? (i - 2) & M : (i + 2) & M;
    int ca = (i - 1) & M;
    int cb = odd ? (i - 2) & M : i;

    float4 c0 = g_C[i];
    float4 cL = g_C[255 * NN + i];

    float4 qa[2], qb[2], q2[2];
#pragma unroll
    for (int p = 0; p < 2; p++) {
        qa[p] = g_C[(2 * p + 1) * NN + ca];
        qb[p] = g_C[(2 * p + 1) * NN + cb];
        q2[p] = g_C[(2 * p + 2) * NN + i];
    }
    __syncthreads();

    float2 (*A)[NN] = bufA;
    float2 (*Bx)[NN] = bufB;

    // ---- layer 0 (s=0)
    {
        u64 D1 = pack2(c0.x, c0.y), D2 = pack2(-c0.y, c0.x);
        u64 O1 = pack2(c0.z, c0.w), O2 = pack2(-c0.w, c0.z);
#pragma unroll
        for (int r = 0; r < RB; r++) {
            float2 t = A[r][i], u = A[r][i ^ 1];
            u64 w;
            MUL_F32X2(w, dup2(t.x), D1);
            FMA_F32X2(w, dup2(t.y), D2);
            FMA_F32X2(w, dup2(u.x), O1);
            FMA_F32X2(w, dup2(u.y), O2);
            F2U cv; cv.u = w; Bx[r][i] = cv.f;
        }
        __syncthreads();
        float2 (*tmp)[NN] = A; A = Bx; Bx = tmp;
    }

    // ---- 127 fused pairs
    for (int p = 0; p < 127; ++p) {
        int sl = p & 1;
        float4 a4 = qa[sl], b4 = qb[sl], d4 = q2[sl];
        if (p + 2 < 127) {
            int pp = p + 2;
            qa[sl] = g_C[(2 * pp + 1) * NN + ca];
            qb[sl] = g_C[(2 * pp + 1) * NN + cb];
            q2[sl] = g_C[(2 * pp + 2) * NN + i];
        }
        u64 A1 = pack2(a4.x, a4.y), A2 = pack2(-a4.y, a4.x);
        u64 Oa1 = pack2(a4.z, a4.w), Oa2 = pack2(-a4.w, a4.z);
        u64 B1 = pack2(b4.x, b4.y), B2 = pack2(-b4.y, b4.x);
        u64 Ob1 = pack2(b4.z, b4.w), Ob2 = pack2(-b4.w, b4.z);
        u64 D1 = pack2(d4.x, d4.y), D2 = pack2(-d4.y, d4.x);
        u64 Q1 = pack2(d4.z, d4.w), Q2 = pack2(-d4.w, d4.z);
#pragma unroll
        for (int r = 0; r < RB; r++) {
            float2 va0 = A[r][i],  va1 = A[r][xa1];
            float2 vb0 = A[r][xb0], vb1 = A[r][xb1];
            u64 ma, mb, w;
            MUL_F32X2(ma, dup2(va0.x), A1);
            FMA_F32X2(ma, dup2(va0.y), A2);
            FMA_F32X2(ma, dup2(va1.x), Oa1);
            FMA_F32X2(ma, dup2(va1.y), Oa2);
            MUL_F32X2(mb, dup2(vb0.x), B1);
            FMA_F32X2(mb, dup2(vb0.y), B2);
            FMA_F32X2(mb, dup2(vb1.x), Ob1);
            FMA_F32X2(mb, dup2(vb1.y), Ob2);
            F2U fa; fa.u = ma; F2U fb; fb.u = mb;
            MUL_F32X2(w, dup2(fa.f.x), D1);
            FMA_F32X2(w, dup2(fa.f.y), D2);
            FMA_F32X2(w, dup2(fb.f.x), Q1);
            FMA_F32X2(w, dup2(fb.f.y), Q2);
            F2U cv; cv.u = w; Bx[r][i] = cv.f;
        }
        __syncthreads();
        float2 (*tmp)[NN] = A; A = Bx; Bx = tmp;
    }

    // ---- layer 255 (s=+1)
    {
        int ia = (i + 1) & M;
        int ib = ((i ^ 1) + 1) & M;
        u64 D1 = pack2(cL.x, cL.y), D2 = pack2(-cL.y, cL.x);
        u64 O1 = pack2(cL.z, cL.w), O2 = pack2(-cL.w, cL.z);
#pragma unroll
        for (int r = 0; r < RB; r++) {
            float2 t = A[r][ia], u = A[r][ib];
            u64 w;
            MUL_F32X2(w, dup2(t.x), D1);
            FMA_F32X2(w, dup2(t.y), D2);
            FMA_F32X2(w, dup2(u.x), O1);
            FMA_F32X2(w, dup2(u.y), O2);
            F2U cv; cv.u = w; Bx[r][i] = cv.f;
        }
        __syncthreads();
        float2 (*tmp)[NN] = A; A = Bx; Bx = tmp;
    }

    auto store_b = [](__nv_bfloat16* img, int n, int k, __nv_bfloat16 v) {
        uint32_t off = ((uint32_t)k >> 5) * 16384u + SWZ64((uint32_t)(n * 64 + (k & 31) * 2));
        *(__nv_bfloat16*)((char*)img + off) = v;
    };

    int src = (i - 1) & M;
#pragma unroll
    for (int r = 0; r < RB; r++) {
        float2 w = A[r][src];
        int k = r0 + r, n = i;
        __nv_bfloat16 hr = __float2bfloat16(w.x);
        __nv_bfloat16 lr = __float2bfloat16(w.x - __bfloat162float(hr));
        __nv_bfloat16 hi = __float2bfloat16(w.y);
        __nv_bfloat16 li = __float2bfloat16(w.y - __bfloat162float(hi));
        store_b(g_Wrh, n, k, hr);
        store_b(g_Wrl, n, k, lr);
        store_b(g_Wih, n, k, hi);
        store_b(g_Wil, n, k, li);
    }
}

// ---------------- kernel 2.5: no-op spacer ----------------
__global__ void probe_kernel() {}

// ---------------- kernel 3: tcgen05 cg2 GEMM, 3-stage ring, INTERLEAVED Yr/Yi chains ----
#define KC 32
#define SMEM_TMEM 0
#define MB_FULL(s)  (16 + (s) * 8)
#define MB_EMPTY(s) (40 + (s) * 8)
#define MB_LEAD(s)  (64 + (s) * 8)
#define MB_DONE     88
#define XR_H 0
#define XR_L 8192
#define XI_H 16384
#define XI_L 24576
#define WR_H 32768
#define WR_L 40960
#define WI_H 49152
#define WI_L 57344
#define STAGE_SZ 65536
#define STAGE_BASE(s) (1024 + (s) * STAGE_SZ)
#define SMEM_TOTAL (1024 + 3 * STAGE_SZ)
#define NSTG 3

__global__ __launch_bounds__(256, 1) __cluster_dims__(2, 1, 1)
void gemm_tc_kernel(const float* __restrict__ xre, const float* __restrict__ xim,
                    float* __restrict__ out) {
#if HAS_TC
    extern __shared__ char smem[];
    const uint32_t sb = smem_u32(smem);
    int tid = threadIdx.x, wid = tid >> 5, lane = tid & 31;
    int m0 = blockIdx.x * 128;
    uint32_t rank = cluster_rank();

    if (wid == 4) TCGEN05_ALLOC_CG2(sb + SMEM_TMEM, 512);
    if (tid == 0) {
#pragma unroll
        for (int s = 0; s < NSTG; ++s) {
            MBARRIER_INIT(sb + MB_FULL(s), 5);
            MBARRIER_INIT(sb + MB_EMPTY(s), 1);
            MBARRIER_INIT(sb + MB_LEAD(s), 2);
        }
        MBARRIER_INIT(sb + MB_DONE, 1);
    }
    __syncthreads();
    CLUSTER_SYNC();
    uint32_t tmem;
    asm volatile("ld.shared.b32 %0, [%1];" : "=r"(tmem) : "r"(sb + SMEM_TMEM));

    if (wid < 4) {
        // ---- A producer: register-prefetched fp32 -> bf16 hi/lo
        float4 buf[16];
#pragma unroll
        for (int j = 0; j < 16; ++j) {
            int pl = j >> 3;
            int g = (j & 7) * 128 + tid;
            int rr = g >> 3, f4 = g & 7;
            const float* plane = pl ? xim : xre;
            buf[j] = *(const float4*)(plane + (size_t)(m0 + rr) * NN + f4 * 4);
        }
        for (int it = 0; it < 8; ++it) {
            int s = it % NSTG;
            if (it >= NSTG) MBARRIER_WAIT_PARITY(sb + MB_EMPTY(s), ((it - NSTG) / NSTG) & 1);
            uint32_t stage = sb + STAGE_BASE(s);
            int kcn = (it + 1) * KC;
            bool more = (it < 7);
#pragma unroll
            for (int j = 0; j < 16; ++j) {
                int pl = j >> 3;
                int g = (j & 7) * 128 + tid;
                int rr = g >> 3, f4 = g & 7;
                float4 v = buf[j];
                if (more) {
                    const float* plane = pl ? xim : xre;
                    buf[j] = *(const float4*)(plane + (size_t)(m0 + rr) * NN + kcn + f4 * 4);
                }
                BU h0, h1, l0, l1;
                h0.h = __floats2bfloat162_rn(v.x, v.y);
                h1.h = __floats2bfloat162_rn(v.z, v.w);
                float2 f0 = __bfloat1622float2(h0.h), f1 = __bfloat1622float2(h1.h);
                l0.h = __floats2bfloat162_rn(v.x - f0.x, v.y - f0.y);
                l1.h = __floats2bfloat162_rn(v.z - f1.x, v.w - f1.y);
                uint32_t off = SWZ64((uint32_t)(rr * 64 + f4 * 8));
                uint32_t hdst = stage + (pl ? XI_H : XR_H) + off;
                uint32_t ldst = stage + (pl ? XI_L : XR_L) + off;
                asm volatile("st.shared.v2.b32 [%0], {%1,%2};" :: "r"(hdst), "r"(h0.u), "r"(h1.u) : "memory");
                asm volatile("st.shared.v2.b32 [%0], {%1,%2};" :: "r"(ldst), "r"(l0.u), "r"(l1.u) : "memory");
            }
            FENCE_ASYNC_SHARED();
            __syncwarp();
            if (lane == 0) MBARRIER_ARRIVE(sb + MB_FULL(s));
        }
    } else if (wid == 5) {
        // ---- B producer: this CTA's half of each image (rank-offset 8KB slices)
        for (int it = 0; it < 8; ++it) {
            int s = it % NSTG;
            if (it >= NSTG) MBARRIER_WAIT_PARITY(sb + MB_EMPTY(s), ((it - NSTG) / NSTG) & 1);
            if (elect_one_pred()) {
                uint32_t mb = sb + MB_FULL(s);
                uint32_t stage = sb + STAGE_BASE(s);
                size_t co = (size_t)it * 16384 + (size_t)rank * 8192;
                MBARRIER_EXPECT_TX(mb, 32768);
                CP_ASYNC_BULK(stage + WR_H, (const char*)g_Wrh + co, 8192, mb);
                CP_ASYNC_BULK(stage + WR_L, (const char*)g_Wrl + co, 8192, mb);
                CP_ASYNC_BULK(stage + WI_H, (const char*)g_Wih + co, 8192, mb);
                CP_ASYNC_BULK(stage + WI_L, (const char*)g_Wil + co, 8192, mb);
            }
        }
    } else if (wid == 6) {
        // ---- relay: forward local readiness to leader
        for (int it = 0; it < 8; ++it) {
            int s = it % NSTG;
            MBARRIER_WAIT_PARITY(sb + MB_FULL(s), (it / NSTG) & 1);
            if (elect_one_pred()) MBARRIER_ARRIVE_LEADER(sb + MB_LEAD(s));
        }
    } else if (wid == 4 && rank == 0) {
        // ---- MMA warp (leader): INTERLEAVE the two independent accumulator chains
        // (Yr @ tmem+0, Yi @ tmem+256) so the tensor pipe always has an independent
        // dispatch to overlap SS-mode operand reads with — breaks the dependent-
        // latency (~330 cyc) serialization seen in R4-R10.
        const uint32_t IDESC = (1u << 4) | (1u << 7) | (1u << 10) | (32u << 17) | (16u << 24);
        const uint32_t NEG_A = 1u << 13;
        const uint32_t aoffs[6] = {XR_H, XR_L, XR_H, XI_H, XI_L, XI_H};
        const uint32_t boffr[6] = {WR_H, WR_H, WR_L, WI_H, WI_H, WI_L};   // Yr (g>=3: neg A)
        const uint32_t boffi[6] = {WI_H, WI_H, WI_L, WR_H, WR_H, WR_L};   // Yi
        uint64_t dbase[NSTG];
#pragma unroll
        for (int s = 0; s < NSTG; ++s) dbase[s] = make_desc_sw64(sb + STAGE_BASE(s));
        for (int it = 0; it < 8; ++it) {
            int s = it % NSTG;
            MBARRIER_WAIT_PARITY_CLU(sb + MB_LEAD(s), (it / NSTG) & 1);
            if (elect_one_pred()) {
                uint64_t db = dbase[s];
#pragma unroll
                for (int g = 0; g < 6; ++g) {
                    uint32_t idr = IDESC | ((g >= 3) ? NEG_A : 0u);
#pragma unroll
                    for (int kk = 0; kk < 2; ++kk) {
                        uint64_t ad = db + (aoffs[g] >> 4) + kk * 2;
                        uint32_t en = !(it == 0 && g == 0 && kk == 0);
                        mma_f16_ss_cg2(tmem,       ad, db + (boffr[g] >> 4) + kk * 2, idr,   en);
                        mma_f16_ss_cg2(tmem + 256, ad, db + (boffi[g] >> 4) + kk * 2, IDESC, en);
                    }
                }
                TCGEN05_COMMIT_MC_CG2((it == 7) ? (sb + MB_DONE) : (sb + MB_EMPTY(s)), 0x3);
            }
        }
    }
    // warp 7 (and rank1 warp 4): fall through to epilogue wait

    // ---- epilogue
    MBARRIER_WAIT_PARITY(sb + MB_DONE, 0);
    TCGEN05_FENCE_AFTER();
    {
        int wg = tid >> 7;
        int wt = tid & 127;
        int m = m0 + wt;
        float* dst = out + (size_t)wg * BB * NN + (size_t)m * NN;
        uint32_t colbase = tmem + wg * 256;
#pragma unroll
        for (int c = 0; c < 8; ++c) {
            uint32_t r[32];
            TCGEN05_LD_32X32B_X32(r, colbase + c * 32);
            TCGEN05_WAIT_LD();
            float4* d4 = (float4*)(dst + c * 32);
#pragma unroll
            for (int q = 0; q < 8; ++q)
                d4[q] = make_float4(__uint_as_float(r[4 * q]), __uint_as_float(r[4 * q + 1]),
                                    __uint_as_float(r[4 * q + 2]), __uint_as_float(r[4 * q + 3]));
        }
    }
    __syncthreads();
    if (wid == 4) {
        TCGEN05_RELINQ_CG2();
        TCGEN05_DEALLOC_CG2(tmem, 512);
    }
    CLUSTER_SYNC();
#endif  // HAS_TC
}

// ---------------- launch ----------------
extern "C" void kernel_launch(void* const* d_in, const int* in_sizes, int n_in,
                              void* d_out, int out_size) {
    const float* x_re  = (const float*)d_in[0];
    const float* x_im  = (const float*)d_in[1];
    const float* theta = (const float*)d_in[2];
    const float* phi   = (const float*)d_in[3];
    const float* gamma = (const float*)d_in[4];
    float* out = (float*)d_out;

    cudaFuncSetAttribute(gemm_tc_kernel, cudaFuncAttributeMaxDynamicSharedMemorySize, SMEM_TOTAL);

    coeff_kernel<<<LL, NN>>>(theta, phi);
    build_w_kernel<<<NN / RB, NN>>>(gamma);
    probe_kernel<<<1, 32>>>();
    gemm_tc_kernel<<<BB / 128, 256, SMEM_TOTAL>>>(x_re, x_im, out);
}